// round 7
// baseline (speedup 1.0000x reference)
#include <cuda_runtime.h>
#include <cuda_bf16.h>

// Problem constants
#define NN   128      // sequence length
#define BB   8        // batch
#define EE   256      // embed dim
#define HH   256      // hidden dim (seq GRU)
#define SS   256      // segment dim
#define TSEG 32       // segment window length
#define G3   768      // 3*H == 3*S (gate dim)
#define TWOH 512      // 2*H == 2*S
#define TRI_CNT  8256                  // N*(N+1)/2
#define OUT_TRI  33816576              // TRI_CNT*B*2S
#define OUT_TOTAL 33820672             // + B*2S (hidden)

typedef unsigned long long ull;

// ------------------------------- scratch -----------------------------------
__device__ float g_x[NN*BB*EE];          // embedded inputs (N*B, E)
__device__ float g_gi_f[NN*BB*G3];       // forward  seq input gates
__device__ float g_gi_r[NN*BB*G3];       // backward seq input gates (step-indexed)
__device__ float g_seqout[NN*BB*TWOH];   // bidirectional GRU outputs (N,B,2H)
__device__ float g_G[NN*BB*G3];          // segment input gates per column j
__device__ float g_h[2*2*BB*HH];         // [parity][dir][b][h] double-buffered seq state
__device__ unsigned int g_ctr;           // grid barrier counter

__device__ __forceinline__ float sigmf(float x)    { return 1.f/(1.f+__expf(-x)); }
__device__ __forceinline__ float tanhfast(float x) { return 2.f/(1.f+__expf(-2.f*x)) - 1.f; }

// packed fp32x2 FMA (Blackwell FFMA2): d = a*b + d, per 32-bit lane
__device__ __forceinline__ void ffma2(ull &d, ull a, ull b){
    asm("fma.rn.f32x2 %0, %1, %2, %0;" : "+l"(d) : "l"(a), "l"(b));
}
__device__ __forceinline__ float hsum2(ull v){
    float lo, hi;
    asm("mov.b64 {%0,%1}, %2;" : "=f"(lo), "=f"(hi) : "l"(v));
    return lo + hi;
}

// release arrive / acquire poll for the grid barrier (no full membar)
__device__ __forceinline__ void bar_arrive(unsigned int* ctr){
    asm volatile("red.release.gpu.global.add.u32 [%0], 1;" :: "l"(ctr) : "memory");
}
__device__ __forceinline__ unsigned int ld_acq(const unsigned int* p){
    unsigned int v;
    asm volatile("ld.acquire.gpu.global.u32 %0, [%1];" : "=r"(v) : "l"(p) : "memory");
    return v;
}

// ----------------------- init (zero) + embedding ----------------------------
__global__ void k_init_embed(float* __restrict__ out,
                             const int* __restrict__ tokens,
                             const float* __restrict__ emb)
{
    long tid    = (long)blockIdx.x*blockDim.x + threadIdx.x;
    long stride = (long)gridDim.x*blockDim.x;
    float4 z = make_float4(0.f,0.f,0.f,0.f);
    float4* o4 = (float4*)out;
    for (long i=tid; i < OUT_TOTAL/4; i+=stride) o4[i] = z;
    if (tid < 2*2*BB*HH) g_h[tid] = 0.f;
    if (tid == 0) g_ctr = 0u;
    // embedding: blocks 0..1023 each copy one (n,b) row of 256 floats
    if (blockIdx.x < NN*BB){
        int m = blockIdx.x;
        int tok = tokens[m];
        g_x[(long)m*EE + threadIdx.x] = __ldg(emb + (long)tok*EE + threadIdx.x);
    }
}

// ------------------------------- NT GEMM ------------------------------------
// C[m][n] = bias[n] + dot(A[m,0:K], W[n,0:K]);  N fixed = 768.
__global__ __launch_bounds__(256) void k_gemm(int mode, const float* __restrict__ W,
                                              const float* __restrict__ bias, int K)
{
    const float* A; float* C; int rev = 0;
    if (mode == 0)      { A = g_x;      C = g_gi_f; }
    else if (mode == 1) { A = g_x;      C = g_gi_r; rev = 1; }
    else                { A = g_seqout; C = g_G;    }

    __shared__ float As[16][68];
    __shared__ float Ws[16][68];
    int bm = blockIdx.y*64, bn = blockIdx.x*64;
    int tid = threadIdx.x;
    int tx = tid & 15, ty = tid >> 4;
    float acc[4][4];
    #pragma unroll
    for (int i=0;i<4;i++)
        #pragma unroll
        for (int j=0;j<4;j++) acc[i][j]=0.f;

    int lr = tid >> 2, lk = (tid & 3) << 2;
    const float* Ap = A + (long)(bm+lr)*K + lk;
    const float* Wp = W + (long)(bn+lr)*K + lk;

    for (int k0=0;k0<K;k0+=16){
        float4 av = *(const float4*)(Ap + k0);
        float4 wv = __ldg((const float4*)(Wp + k0));
        As[lk+0][lr]=av.x; As[lk+1][lr]=av.y; As[lk+2][lr]=av.z; As[lk+3][lr]=av.w;
        Ws[lk+0][lr]=wv.x; Ws[lk+1][lr]=wv.y; Ws[lk+2][lr]=wv.z; Ws[lk+3][lr]=wv.w;
        __syncthreads();
        #pragma unroll
        for (int k=0;k<16;k++){
            float a0=As[k][ty*4+0], a1=As[k][ty*4+1], a2=As[k][ty*4+2], a3=As[k][ty*4+3];
            float b0=Ws[k][tx*4+0], b1=Ws[k][tx*4+1], b2=Ws[k][tx*4+2], b3=Ws[k][tx*4+3];
            acc[0][0]+=a0*b0; acc[0][1]+=a0*b1; acc[0][2]+=a0*b2; acc[0][3]+=a0*b3;
            acc[1][0]+=a1*b0; acc[1][1]+=a1*b1; acc[1][2]+=a1*b2; acc[1][3]+=a1*b3;
            acc[2][0]+=a2*b0; acc[2][1]+=a2*b1; acc[2][2]+=a2*b2; acc[2][3]+=a2*b3;
            acc[3][0]+=a3*b0; acc[3][1]+=a3*b1; acc[3][2]+=a3*b2; acc[3][3]+=a3*b3;
        }
        __syncthreads();
    }
    #pragma unroll
    for (int i=0;i<4;i++){
        int m  = bm + ty*4 + i;
        int mo = m;
        if (rev){ int t = m >> 3, b = m & 7; mo = ((NN-1-t)<<3) | b; }
        #pragma unroll
        for (int j=0;j<4;j++){
            int n = bn + tx*4 + j;
            C[(long)mo*G3 + n] = acc[i][j] + __ldg(bias + n);
        }
    }
}

// -------------------------- bidirectional seq GRU ---------------------------
// 128 CTAs x 256 thr. Unit=(dir,b,j): 4096 units, 8 threads/unit (K split 32).
// Weights register-resident. Release/acquire grid barrier per step.
__global__ __launch_bounds__(256) void k_seqgru(const float* __restrict__ Whf,
                                                const float* __restrict__ Whr,
                                                const float* __restrict__ bhf,
                                                const float* __restrict__ bhr)
{
    int gt  = blockIdx.x*256 + threadIdx.x;
    int q   = gt & 7;
    int u   = gt >> 3;
    int j   = u & 255;
    int b   = (u >> 8) & 7;
    int dir = (u >> 11) & 1;
    const float* Wh = dir ? Whr : Whf;
    const float* bh = dir ? bhr : bhf;
    const float* gi = dir ? g_gi_r : g_gi_f;
    int k0 = q*32;

    float wr[32], wz[32], wn[32];
    const float* pr = Wh + (long)(0*HH + j)*HH + k0;
    const float* pz = Wh + (long)(1*HH + j)*HH + k0;
    const float* pn = Wh + (long)(2*HH + j)*HH + k0;
    #pragma unroll
    for (int kk=0;kk<32;kk+=4){
        float4 v;
        v = __ldg((const float4*)(pr+kk)); wr[kk]=v.x; wr[kk+1]=v.y; wr[kk+2]=v.z; wr[kk+3]=v.w;
        v = __ldg((const float4*)(pz+kk)); wz[kk]=v.x; wz[kk+1]=v.y; wz[kk+2]=v.z; wz[kk+3]=v.w;
        v = __ldg((const float4*)(pn+kk)); wn[kk]=v.x; wn[kk+1]=v.y; wn[kk+2]=v.z; wn[kk+3]=v.w;
    }
    float br  = __ldg(bh + j);
    float bz  = __ldg(bh + HH + j);
    float bn_ = __ldg(bh + 2*HH + j);

    unsigned int target = 0;
    for (int t=0; t<NN; t++){
        const float* hc = g_h + (((t&1)<<1) | dir)*(BB*HH) + b*HH;
        float sr=0.f, sz=0.f, sn=0.f;
        #pragma unroll
        for (int kk=0;kk<32;kk+=4){
            float4 hv = __ldcg((const float4*)(hc + k0 + kk));
            sr += wr[kk]*hv.x + wr[kk+1]*hv.y + wr[kk+2]*hv.z + wr[kk+3]*hv.w;
            sz += wz[kk]*hv.x + wz[kk+1]*hv.y + wz[kk+2]*hv.z + wz[kk+3]*hv.w;
            sn += wn[kk]*hv.x + wn[kk+1]*hv.y + wn[kk+2]*hv.z + wn[kk+3]*hv.w;
        }
        #pragma unroll
        for (int off=1; off<8; off<<=1){
            sr += __shfl_xor_sync(0xffffffffu, sr, off);
            sz += __shfl_xor_sync(0xffffffffu, sz, off);
            sn += __shfl_xor_sync(0xffffffffu, sn, off);
        }
        const float* gib = gi + (long)((t<<3) + b)*G3;
        float gr = __ldg(gib + j);
        float gz = __ldg(gib + HH + j);
        float gn = __ldg(gib + 2*HH + j);
        float hold = __ldcg(hc + j);

        float r  = sigmf(gr + sr + br);
        float z  = sigmf(gz + sz + bz);
        float ng = tanhfast(gn + r*(sn + bn_));
        float hn = (1.f - z)*ng + z*hold;

        if (q == 0){
            __stcg(g_h + ((((t+1)&1)<<1) | dir)*(BB*HH) + b*HH + j, hn);
            int row = dir ? (NN-1-t) : t;
            g_seqout[(long)((row<<3)+b)*TWOH + (dir<<8) + j] = hn;
        }

        // grid barrier (all 128 CTAs co-resident); release arrive, acquire poll
        target += 128;
        __syncthreads();
        if (threadIdx.x == 0){
            bar_arrive(&g_ctr);
            while (ld_acq(&g_ctr) < target) { }
        }
        __syncthreads();
    }
}

// ----------------------------- segment GRUs ---------------------------------
// 128 CTAs, 512 threads: thread = (dir, c). Thread (dir,c) owns gate column c
// of its direction's chain for all 8 batch rows (24 fp32x2 accumulators).
// h in smem (broadcast reads); Wh streamed via L1/L2 (dir0/dir1 share rows ->
// L1 hits); inner product with packed fp32x2 FFMA2.
__global__ __launch_bounds__(512) void k_seg(const float* __restrict__ Whs,
                                             const float* __restrict__ bhs,
                                             const float* __restrict__ h0f,
                                             const float* __restrict__ h0b,
                                             float* __restrict__ out)
{
    int i   = blockIdx.x;
    int tid = threadIdx.x;
    int c   = tid & 255;
    int dir = tid >> 8;

    __shared__ __align__(16) float hbuf[2][BB][SS];

    const float* h0F = h0f + (long)i*BB*SS;
    const float* h0B = h0b + (long)i*BB*SS;
    for (int idx=tid; idx<BB*SS; idx+=512){
        ((float*)hbuf[0])[idx] = h0F[idx];
        ((float*)hbuf[1])[idx] = h0B[idx];
    }

    const float* wr = Whs + (long)(0*SS + c)*SS;
    const float* wz = Whs + (long)(1*SS + c)*SS;
    const float* wn = Whs + (long)(2*SS + c)*SS;
    float br  = __ldg(bhs + c);
    float bz  = __ldg(bhs + SS + c);
    float bn_ = __ldg(bhs + 2*SS + c);
    __syncthreads();

    const float (*hb)[SS] = hbuf[dir];

    for (int t=0; t<TSEG; t++){
        int j = dir ? max(i-t, 0) : min(i+t, NN-1);
        const float* Gj = g_G + (long)j*BB*G3;

        ull aR[BB], aZ[BB], aN[BB];
        #pragma unroll
        for (int b=0;b<BB;b++){ aR[b]=0ull; aZ[b]=0ull; aN[b]=0ull; }

        #pragma unroll 2
        for (int k=0;k<SS;k+=4){
            ulonglong2 r2 = __ldg((const ulonglong2*)(wr+k));
            ulonglong2 z2 = __ldg((const ulonglong2*)(wz+k));
            ulonglong2 n2 = __ldg((const ulonglong2*)(wn+k));
            #pragma unroll
            for (int b=0;b<BB;b++){
                ulonglong2 h2 = *(const ulonglong2*)(&hb[b][k]);
                ffma2(aR[b], r2.x, h2.x); ffma2(aR[b], r2.y, h2.y);
                ffma2(aZ[b], z2.x, h2.x); ffma2(aZ[b], z2.y, h2.y);
                ffma2(aN[b], n2.x, h2.x); ffma2(aN[b], n2.y, h2.y);
            }
        }

        float hnew[BB];
        #pragma unroll
        for (int b=0;b<BB;b++){
            float sr = hsum2(aR[b]);
            float sz = hsum2(aZ[b]);
            float sn = hsum2(aN[b]);
            float hold = hb[b][c];
            float r  = sigmf(__ldg(Gj + b*G3        + c) + sr + br);
            float z  = sigmf(__ldg(Gj + b*G3 + SS   + c) + sz + bz);
            float ng = tanhfast(__ldg(Gj + b*G3 + 2*SS + c) + r*(sn + bn_));
            hnew[b] = (1.f - z)*ng + z*hold;
        }
        __syncthreads();                 // all reads of old h done
        #pragma unroll
        for (int b=0;b<BB;b++) hbuf[dir][b][c] = hnew[b];

        bool valid = dir ? (i-t >= 0) : (i+t < NN);
        if (valid){
            int row = dir ? (i-t) : i;
            int col = dir ? i     : (i+t);
            long idx = (long)row*NN - (long)row*(row-1)/2 + (col-row);
            float* dst = out + idx*(BB*TWOH) + (dir<<8) + c;
            #pragma unroll
            for (int b=0;b<BB;b++) dst[b*TWOH] = hnew[b];
        }
        if (i == NN-1 && ((dir==0 && t==0) || (dir==1 && t==TSEG-1))){
            float* hd = out + OUT_TRI + (dir<<8) + c;
            #pragma unroll
            for (int b=0;b<BB;b++) hd[b*TWOH] = hnew[b];
        }
        __syncthreads();                 // new h visible before next step
    }
}

// ------------------------------- launcher -----------------------------------
extern "C" void kernel_launch(void* const* d_in, const int* in_sizes, int n_in,
                              void* d_out, int out_size)
{
    const int*   tokens = (const int*)  d_in[0];
    const float* emb    = (const float*)d_in[1];
    const float* Wi_f   = (const float*)d_in[2];
    const float* Wh_f   = (const float*)d_in[3];
    const float* bi_f   = (const float*)d_in[4];
    const float* bh_f   = (const float*)d_in[5];
    const float* Wi_r   = (const float*)d_in[6];
    const float* Wh_r   = (const float*)d_in[7];
    const float* bi_r   = (const float*)d_in[8];
    const float* bh_r   = (const float*)d_in[9];
    const float* Wi_s   = (const float*)d_in[10];
    const float* Wh_s   = (const float*)d_in[11];
    const float* bi_s   = (const float*)d_in[12];
    const float* bh_s   = (const float*)d_in[13];
    const float* h0f    = (const float*)d_in[14];
    const float* h0b    = (const float*)d_in[15];
    float* out = (float*)d_out;

    k_init_embed<<<4096, 256>>>(out, tokens, emb);      // 1

    dim3 gg(G3/64, (NN*BB)/64);                          // (12, 16)
    k_gemm<<<gg, 256>>>(0, Wi_f, bi_f, EE);              // 2
    k_gemm<<<gg, 256>>>(1, Wi_r, bi_r, EE);              // 3

    k_seqgru<<<128, 256>>>(Wh_f, Wh_r, bh_f, bh_r);      // 4

    k_gemm<<<gg, 256>>>(2, Wi_s, bi_s, TWOH);            // 5

    k_seg<<<128, 512>>>(Wh_s, bh_s, h0f, h0b, out);      // 6
}

// round 8
// speedup vs baseline: 1.3889x; 1.3889x over previous
#include <cuda_runtime.h>
#include <cuda_bf16.h>

// Problem constants
#define NN   128      // sequence length
#define BB   8        // batch
#define EE   256      // embed dim
#define HH   256      // hidden dim (seq GRU)
#define SS   256      // segment dim
#define TSEG 32       // segment window length
#define G3   768      // 3*H == 3*S (gate dim)
#define TWOH 512      // 2*H == 2*S
#define TRI_CNT  8256                  // N*(N+1)/2
#define OUT_TRI  33816576              // TRI_CNT*B*2S
#define OUT_TOTAL 33820672             // + B*2S (hidden)

typedef unsigned long long ull;

// ------------------------------- scratch -----------------------------------
__device__ float g_x[NN*BB*EE];          // embedded inputs (N*B, E)
__device__ float g_gi_f[NN*BB*G3];       // forward  seq input gates
__device__ float g_gi_r[NN*BB*G3];       // backward seq input gates (step-indexed)
__device__ float g_seqout[NN*BB*TWOH];   // bidirectional GRU outputs (N,B,2H)
__device__ float g_G[NN*BB*G3];          // segment input gates per column j
__device__ float g_h[2*2*BB*HH];         // [parity][dir][b][h] double-buffered seq state
__device__ float g_WT[SS*G3];            // transposed segment weights: WT[k][gate*256+c]
__device__ unsigned int g_ctrs[16*32];   // per-(dir,b) barrier counters, 128B apart

__device__ __forceinline__ float sigmf(float x)    { return 1.f/(1.f+__expf(-x)); }
__device__ __forceinline__ float tanhfast(float x) { return 2.f/(1.f+__expf(-2.f*x)) - 1.f; }

// packed fp32x2 FMA (Blackwell FFMA2): d = a*b + d, per 32-bit lane
__device__ __forceinline__ void ffma2(ull &d, ull a, ull b){
    asm("fma.rn.f32x2 %0, %1, %2, %0;" : "+l"(d) : "l"(a), "l"(b));
}
__device__ __forceinline__ float hsum2(ull v){
    float lo, hi;
    asm("mov.b64 {%0,%1}, %2;" : "=f"(lo), "=f"(hi) : "l"(v));
    return lo + hi;
}
__device__ __forceinline__ ull pack2(float lo, float hi){
    ull d;
    asm("mov.b64 %0, {%1,%2};" : "=l"(d) : "f"(lo), "f"(hi));
    return d;
}

// release arrive / acquire poll for the group barriers (no full membar)
__device__ __forceinline__ void bar_arrive(unsigned int* ctr){
    asm volatile("red.release.gpu.global.add.u32 [%0], 1;" :: "l"(ctr) : "memory");
}
__device__ __forceinline__ unsigned int ld_acq(const unsigned int* p){
    unsigned int v;
    asm volatile("ld.acquire.gpu.global.u32 %0, [%1];" : "=r"(v) : "l"(p) : "memory");
    return v;
}

// ----------------------- init (zero) + embedding ----------------------------
__global__ void k_init_embed(float* __restrict__ out,
                             const int* __restrict__ tokens,
                             const float* __restrict__ emb)
{
    long tid    = (long)blockIdx.x*blockDim.x + threadIdx.x;
    long stride = (long)gridDim.x*blockDim.x;
    float4 z = make_float4(0.f,0.f,0.f,0.f);
    float4* o4 = (float4*)out;
    for (long i=tid; i < OUT_TOTAL/4; i+=stride) o4[i] = z;
    if (tid < 2*2*BB*HH) g_h[tid] = 0.f;
    if (tid < 16*32)     g_ctrs[tid] = 0u;
    // embedding: blocks 0..1023 each copy one (n,b) row of 256 floats
    if (blockIdx.x < NN*BB){
        int m = blockIdx.x;
        int tok = tokens[m];
        g_x[(long)m*EE + threadIdx.x] = __ldg(emb + (long)tok*EE + threadIdx.x);
    }
}

// --------------------- transpose segment weights ----------------------------
// Whs[row][k] (768 x 256) -> g_WT[k][row] (256 x 768), tiled through smem.
__global__ __launch_bounds__(256) void k_transpose(const float* __restrict__ Whs)
{
    __shared__ float tile[32][33];
    int tk = blockIdx.x*32;          // k-block   (0..224)
    int tr = blockIdx.y*32;          // row-block (0..736)
    int tx = threadIdx.x & 31, ty = threadIdx.x >> 5;   // 32 x 8
    #pragma unroll
    for (int r=ty; r<32; r+=8)
        tile[r][tx] = __ldg(Whs + (long)(tr+r)*SS + tk + tx);
    __syncthreads();
    #pragma unroll
    for (int k=ty; k<32; k+=8)
        g_WT[(long)(tk+k)*G3 + tr + tx] = tile[tx][k];
}

// ------------------------------- NT GEMM ------------------------------------
// C[m][n] = bias[n] + dot(A[m,0:K], W[n,0:K]);  N fixed = 768.
__global__ __launch_bounds__(256) void k_gemm(int mode, const float* __restrict__ W,
                                              const float* __restrict__ bias, int K)
{
    const float* A; float* C; int rev = 0;
    if (mode == 0)      { A = g_x;      C = g_gi_f; }
    else if (mode == 1) { A = g_x;      C = g_gi_r; rev = 1; }
    else                { A = g_seqout; C = g_G;    }

    __shared__ float As[16][68];
    __shared__ float Ws[16][68];
    int bm = blockIdx.y*64, bn = blockIdx.x*64;
    int tid = threadIdx.x;
    int tx = tid & 15, ty = tid >> 4;
    float acc[4][4];
    #pragma unroll
    for (int i=0;i<4;i++)
        #pragma unroll
        for (int j=0;j<4;j++) acc[i][j]=0.f;

    int lr = tid >> 2, lk = (tid & 3) << 2;
    const float* Ap = A + (long)(bm+lr)*K + lk;
    const float* Wp = W + (long)(bn+lr)*K + lk;

    for (int k0=0;k0<K;k0+=16){
        float4 av = *(const float4*)(Ap + k0);
        float4 wv = __ldg((const float4*)(Wp + k0));
        As[lk+0][lr]=av.x; As[lk+1][lr]=av.y; As[lk+2][lr]=av.z; As[lk+3][lr]=av.w;
        Ws[lk+0][lr]=wv.x; Ws[lk+1][lr]=wv.y; Ws[lk+2][lr]=wv.z; Ws[lk+3][lr]=wv.w;
        __syncthreads();
        #pragma unroll
        for (int k=0;k<16;k++){
            float a0=As[k][ty*4+0], a1=As[k][ty*4+1], a2=As[k][ty*4+2], a3=As[k][ty*4+3];
            float b0=Ws[k][tx*4+0], b1=Ws[k][tx*4+1], b2=Ws[k][tx*4+2], b3=Ws[k][tx*4+3];
            acc[0][0]+=a0*b0; acc[0][1]+=a0*b1; acc[0][2]+=a0*b2; acc[0][3]+=a0*b3;
            acc[1][0]+=a1*b0; acc[1][1]+=a1*b1; acc[1][2]+=a1*b2; acc[1][3]+=a1*b3;
            acc[2][0]+=a2*b0; acc[2][1]+=a2*b1; acc[2][2]+=a2*b2; acc[2][3]+=a2*b3;
            acc[3][0]+=a3*b0; acc[3][1]+=a3*b1; acc[3][2]+=a3*b2; acc[3][3]+=a3*b3;
        }
        __syncthreads();
    }
    #pragma unroll
    for (int i=0;i<4;i++){
        int m  = bm + ty*4 + i;
        int mo = m;
        if (rev){ int t = m >> 3, b = m & 7; mo = ((NN-1-t)<<3) | b; }
        #pragma unroll
        for (int j=0;j<4;j++){
            int n = bn + tx*4 + j;
            C[(long)mo*G3 + n] = acc[i][j] + __ldg(bias + n);
        }
    }
}

// -------------------------- bidirectional seq GRU ---------------------------
// 128 CTAs x 256 thr. Unit=(dir,b,j): 4096 units, 8 threads/unit (K split 32).
// Weights register-resident. Each CTA belongs to exactly one (dir,b) group of
// 8 CTAs; per-group release/acquire barrier (padded counters) per step.
__global__ __launch_bounds__(256) void k_seqgru(const float* __restrict__ Whf,
                                                const float* __restrict__ Whr,
                                                const float* __restrict__ bhf,
                                                const float* __restrict__ bhr)
{
    int gt  = blockIdx.x*256 + threadIdx.x;
    int q   = gt & 7;
    int u   = gt >> 3;
    int j   = u & 255;
    int b   = (u >> 8) & 7;
    int dir = (u >> 11) & 1;
    const float* Wh = dir ? Whr : Whf;
    const float* bh = dir ? bhr : bhf;
    const float* gi = dir ? g_gi_r : g_gi_f;
    int k0 = q*32;
    unsigned int* ctr = &g_ctrs[(blockIdx.x >> 3)*32];   // group = (dir<<3)|b

    float wr[32], wz[32], wn[32];
    const float* pr = Wh + (long)(0*HH + j)*HH + k0;
    const float* pz = Wh + (long)(1*HH + j)*HH + k0;
    const float* pn = Wh + (long)(2*HH + j)*HH + k0;
    #pragma unroll
    for (int kk=0;kk<32;kk+=4){
        float4 v;
        v = __ldg((const float4*)(pr+kk)); wr[kk]=v.x; wr[kk+1]=v.y; wr[kk+2]=v.z; wr[kk+3]=v.w;
        v = __ldg((const float4*)(pz+kk)); wz[kk]=v.x; wz[kk+1]=v.y; wz[kk+2]=v.z; wz[kk+3]=v.w;
        v = __ldg((const float4*)(pn+kk)); wn[kk]=v.x; wn[kk+1]=v.y; wn[kk+2]=v.z; wn[kk+3]=v.w;
    }
    float br  = __ldg(bh + j);
    float bz  = __ldg(bh + HH + j);
    float bn_ = __ldg(bh + 2*HH + j);

    unsigned int target = 0;
    for (int t=0; t<NN; t++){
        const float* hc = g_h + (((t&1)<<1) | dir)*(BB*HH) + b*HH;
        float sr=0.f, sz=0.f, sn=0.f;
        #pragma unroll
        for (int kk=0;kk<32;kk+=4){
            float4 hv = __ldcg((const float4*)(hc + k0 + kk));
            sr += wr[kk]*hv.x + wr[kk+1]*hv.y + wr[kk+2]*hv.z + wr[kk+3]*hv.w;
            sz += wz[kk]*hv.x + wz[kk+1]*hv.y + wz[kk+2]*hv.z + wz[kk+3]*hv.w;
            sn += wn[kk]*hv.x + wn[kk+1]*hv.y + wn[kk+2]*hv.z + wn[kk+3]*hv.w;
        }
        #pragma unroll
        for (int off=1; off<8; off<<=1){
            sr += __shfl_xor_sync(0xffffffffu, sr, off);
            sz += __shfl_xor_sync(0xffffffffu, sz, off);
            sn += __shfl_xor_sync(0xffffffffu, sn, off);
        }
        const float* gib = gi + (long)((t<<3) + b)*G3;
        float gr = __ldg(gib + j);
        float gz = __ldg(gib + HH + j);
        float gn = __ldg(gib + 2*HH + j);
        float hold = __ldcg(hc + j);

        float r  = sigmf(gr + sr + br);
        float z  = sigmf(gz + sz + bz);
        float ng = tanhfast(gn + r*(sn + bn_));
        float hn = (1.f - z)*ng + z*hold;

        if (q == 0){
            __stcg(g_h + ((((t+1)&1)<<1) | dir)*(BB*HH) + b*HH + j, hn);
            int row = dir ? (NN-1-t) : t;
            g_seqout[(long)((row<<3)+b)*TWOH + (dir<<8) + j] = hn;
        }

        // group barrier (8 co-resident CTAs of this (dir,b) chain)
        target += 8;
        __syncthreads();
        if (threadIdx.x == 0){
            bar_arrive(ctr);
            while (ld_acq(ctr) < target) { }
        }
        __syncthreads();
    }
}

// ----------------------------- segment GRUs ---------------------------------
// 128 CTAs: CTA i handles BOTH direction chains for start i. Thread c owns
// gate column c for all 8 batch rows of both chains. h in smem (broadcast
// reads), weights read COALESCED from the transposed copy g_WT[k][gate*256+c],
// inner product with packed fp32x2 FFMA2.
__global__ __launch_bounds__(256) void k_seg(const float* __restrict__ bhs,
                                             const float* __restrict__ h0f,
                                             const float* __restrict__ h0b,
                                             float* __restrict__ out)
{
    int i = blockIdx.x;
    int c = threadIdx.x;

    __shared__ __align__(16) float hbuf[2][BB][SS];

    const float* h0F = h0f + (long)i*BB*SS;
    const float* h0B = h0b + (long)i*BB*SS;
    for (int idx=c; idx<BB*SS; idx+=256){
        ((float*)hbuf[0])[idx] = h0F[idx];
        ((float*)hbuf[1])[idx] = h0B[idx];
    }

    const float* wtc = g_WT + c;      // WT[k][gate*256+c] = wtc[k*G3 + gate*256]
    float br  = __ldg(bhs + c);
    float bz  = __ldg(bhs + SS + c);
    float bn_ = __ldg(bhs + 2*SS + c);
    __syncthreads();

    for (int t=0; t<TSEG; t++){
        int jF = min(i+t, NN-1);
        int jB = max(i-t, 0);
        const float* GF = g_G + (long)jF*BB*G3;
        const float* GB = g_G + (long)jB*BB*G3;

        ull aR[2][BB], aZ[2][BB], aN[2][BB];
        #pragma unroll
        for (int d=0;d<2;d++)
            #pragma unroll
            for (int b=0;b<BB;b++){ aR[d][b]=0ull; aZ[d][b]=0ull; aN[d][b]=0ull; }

        #pragma unroll 2
        for (int k=0;k<SS;k+=4){
            const float* p0 = wtc + (long)k*G3;        // k
            const float* p1 = p0 + G3;                  // k+1
            const float* p2 = p1 + G3;                  // k+2
            const float* p3 = p2 + G3;                  // k+3
            ull rA = pack2(__ldg(p0        ), __ldg(p1        ));
            ull rB = pack2(__ldg(p2        ), __ldg(p3        ));
            ull zA = pack2(__ldg(p0 +   256), __ldg(p1 +   256));
            ull zB = pack2(__ldg(p2 +   256), __ldg(p3 +   256));
            ull nA = pack2(__ldg(p0 +   512), __ldg(p1 +   512));
            ull nB = pack2(__ldg(p2 +   512), __ldg(p3 +   512));
            #pragma unroll
            for (int d=0;d<2;d++){
                #pragma unroll
                for (int b=0;b<BB;b++){
                    ulonglong2 h2 = *(const ulonglong2*)(&hbuf[d][b][k]);
                    ffma2(aR[d][b], rA, h2.x); ffma2(aR[d][b], rB, h2.y);
                    ffma2(aZ[d][b], zA, h2.x); ffma2(aZ[d][b], zB, h2.y);
                    ffma2(aN[d][b], nA, h2.x); ffma2(aN[d][b], nB, h2.y);
                }
            }
        }

        float hnew[2][BB];
        #pragma unroll
        for (int d=0;d<2;d++){
            const float* Gd = d ? GB : GF;
            #pragma unroll
            for (int b=0;b<BB;b++){
                float sr = hsum2(aR[d][b]);
                float sz = hsum2(aZ[d][b]);
                float sn = hsum2(aN[d][b]);
                float hold = hbuf[d][b][c];
                float r  = sigmf(__ldg(Gd + b*G3        + c) + sr + br);
                float z  = sigmf(__ldg(Gd + b*G3 + SS   + c) + sz + bz);
                float ng = tanhfast(__ldg(Gd + b*G3 + 2*SS + c) + r*(sn + bn_));
                hnew[d][b] = (1.f - z)*ng + z*hold;
            }
        }
        __syncthreads();                 // all reads of old h done
        #pragma unroll
        for (int d=0;d<2;d++)
            #pragma unroll
            for (int b=0;b<BB;b++) hbuf[d][b][c] = hnew[d][b];

        if (i+t < NN){                   // forward: row=i, col=i+t
            int row = i, col = i+t;
            long idx = (long)row*NN - (long)row*(row-1)/2 + (col-row);
            float* dst = out + idx*(BB*TWOH) + c;
            #pragma unroll
            for (int b=0;b<BB;b++) dst[b*TWOH] = hnew[0][b];
        }
        if (i-t >= 0){                   // backward: row=i-t, col=i
            int row = i-t, col = i;
            long idx = (long)row*NN - (long)row*(row-1)/2 + (col-row);
            float* dst = out + idx*(BB*TWOH) + SS + c;
            #pragma unroll
            for (int b=0;b<BB;b++) dst[b*TWOH] = hnew[1][b];
        }
        if (i == NN-1){
            if (t == 0){
                float* hd = out + OUT_TRI + c;
                #pragma unroll
                for (int b=0;b<BB;b++) hd[b*TWOH] = hnew[0][b];
            }
            if (t == TSEG-1){
                float* hd = out + OUT_TRI + SS + c;
                #pragma unroll
                for (int b=0;b<BB;b++) hd[b*TWOH] = hnew[1][b];
            }
        }
        __syncthreads();                 // new h visible before next step
    }
}

// ------------------------------- launcher -----------------------------------
extern "C" void kernel_launch(void* const* d_in, const int* in_sizes, int n_in,
                              void* d_out, int out_size)
{
    const int*   tokens = (const int*)  d_in[0];
    const float* emb    = (const float*)d_in[1];
    const float* Wi_f   = (const float*)d_in[2];
    const float* Wh_f   = (const float*)d_in[3];
    const float* bi_f   = (const float*)d_in[4];
    const float* bh_f   = (const float*)d_in[5];
    const float* Wi_r   = (const float*)d_in[6];
    const float* Wh_r   = (const float*)d_in[7];
    const float* bi_r   = (const float*)d_in[8];
    const float* bh_r   = (const float*)d_in[9];
    const float* Wi_s   = (const float*)d_in[10];
    const float* Wh_s   = (const float*)d_in[11];
    const float* bi_s   = (const float*)d_in[12];
    const float* bh_s   = (const float*)d_in[13];
    const float* h0f    = (const float*)d_in[14];
    const float* h0b    = (const float*)d_in[15];
    float* out = (float*)d_out;

    k_init_embed<<<4096, 256>>>(out, tokens, emb);      // 1

    dim3 gg(G3/64, (NN*BB)/64);                          // (12, 16)
    k_gemm<<<gg, 256>>>(0, Wi_f, bi_f, EE);              // 2
    k_gemm<<<gg, 256>>>(1, Wi_r, bi_r, EE);              // 3

    k_seqgru<<<128, 256>>>(Wh_f, Wh_r, bh_f, bh_r);      // 4 (profiled slot)

    dim3 gt(SS/32, G3/32);                               // (8, 24)
    k_transpose<<<gt, 256>>>(Wh_s);                      // 5

    k_gemm<<<gg, 256>>>(2, Wi_s, bi_s, TWOH);            // 6

    k_seg<<<128, 256>>>(bh_s, h0f, h0b, out);            // 7
}